// round 8
// baseline (speedup 1.0000x reference)
#include <cuda_runtime.h>
#include <cstdint>

// SemiConv2d: 5x5 max-plus dilation, 'same' padding with -inf.
// input:  (16, 64, 256, 256) fp32 -> 1024 independent 256x256 images
// kernel: (5, 5) fp32
//
// Row-streaming, 5 rotating accumulator slots, 4 cols/thread (float4 I/O),
// software-prefetched double-buffered loads (R6), boundary peeling (R7).
// R8 change: SINGLE BALANCED WAVE *with* prefetch. 128-row strips -> 4096
// warp-tasks = 1024 blocks x 128 thr; regs=48 allows 10 blocks/SM so all
// blocks are co-resident in one wave ({7,6} blocks/SM, ~1% imbalance),
// removing the 568-block ragged second wave that capped achieved occupancy
// at 48.9%. R5 tested this grid WITHOUT prefetch and lost to latency
// exposure; prefetch (R6) removed that dependence.

#define IMG_H 256
#define IMG_W 256

__device__ __align__(16) float g_ninf[16];

__global__ void fill_ninf_kernel() {
    g_ninf[threadIdx.x] = __int_as_float(0xff800000u);
}

__global__ void __launch_bounds__(128) dil5x5_kernel(
    const float* __restrict__ x,
    const float* __restrict__ kw,
    float* __restrict__ out)
{
    const int lane   = threadIdx.x & 31;
    const int wlocal = threadIdx.x >> 5;
    const int w      = blockIdx.x * 4 + wlocal;   // warp-task id, 0..4095

    const int img   = w >> 2;          // 0..1023
    const int strip = (w >> 1) & 1;    // 0..1  -> 128-row strip
    const int half  = w & 1;           // 0..1  -> 128-col half

    const int i0 = strip << 7;                    // first output row of strip
    const int j0 = (half << 7) + (lane << 2);     // first of 4 output cols

    float k[25];
#pragma unroll
    for (int t = 0; t < 25; ++t) k[t] = kw[t];

    const float NI = __int_as_float(0xff800000u);

    float acc[5][4];
#pragma unroll
    for (int q = 0; q < 5; ++q)
#pragma unroll
        for (int c = 0; c < 4; ++c) acc[q][c] = NI;

    const float* xim = x   + (size_t)img * (IMG_H * IMG_W);
    float*       oim = out + (size_t)img * (IMG_H * IMG_W);

    // Column-halo validity (loop-invariant). A covers cols j0-4..j0-1 (we
    // use j0-2,j0-1): invalid only when j0==0. C covers j0+4..j0+7 (we use
    // j0+4,j0+5): invalid only when j0==252. B always valid.
    const bool c0ok = (j0 != 0);
    const bool c2ok = (j0 != 252);

    // Row-halo validity: rows i0-2,i0-1 exist unless strip==0; rows
    // i0+128,i0+129 exist unless strip==1 (bottom strip).
    const bool topok = (strip != 0);
    const bool botok = (strip != 1);

    const float4 NIV = make_float4(NI, NI, NI, NI);
    float4 Ab[2] = {NIV, NIV}, Bb[2] = {NIV, NIV}, Cb[2] = {NIV, NIV};

    const float* ninf = g_ninf;   // 16 floats of -inf

    // Load a row (base pointer at col j0-4) into buffer DSTP.
#define PREF(DSTP, RP)                                                       \
    {                                                                        \
        const float* _rp = (RP);                                             \
        if (c0ok) Ab[DSTP] = *(const float4*)(_rp);                          \
        Bb[DSTP] = *(const float4*)(_rp + 4);                                \
        if (c2ok) Cb[DSTP] = *(const float4*)(_rp + 8);                      \
    }

    // Apply buffer CUR to the 5 rotating slots (phase PH); optionally store
    // the completed slot (slot PH finishes kernel row u=4 this step).
#define MATH(PH, CUR, STOREF, OPTR)                                          \
    {                                                                        \
        float X[12] = {Ab[CUR].x, Ab[CUR].y, Ab[CUR].z, Ab[CUR].w,           \
                       Bb[CUR].x, Bb[CUR].y, Bb[CUR].z, Bb[CUR].w,           \
                       Cb[CUR].x, Cb[CUR].y, Cb[CUR].z, Cb[CUR].w};          \
        _Pragma("unroll")                                                    \
        for (int q = 0; q < 5; ++q) {                                        \
            const int d = (q - (PH) + 5) % 5;   /* compile-time */           \
            const int u = 4 - d;                /* kernel row   */           \
            if (d == 4) {                                                    \
                _Pragma("unroll")                                            \
                for (int c = 0; c < 4; ++c)                                  \
                    acc[q][c] = X[c + 2] + k[u * 5 + 0];                     \
                _Pragma("unroll")                                            \
                for (int v = 1; v < 5; ++v)                                  \
                    _Pragma("unroll")                                        \
                    for (int c = 0; c < 4; ++c)                              \
                        acc[q][c] = fmaxf(acc[q][c], X[c + v + 2] + k[u * 5 + v]); \
            } else {                                                         \
                _Pragma("unroll")                                            \
                for (int v = 0; v < 5; ++v)                                  \
                    _Pragma("unroll")                                        \
                    for (int c = 0; c < 4; ++c)                              \
                        acc[q][c] = fmaxf(acc[q][c], X[c + v + 2] + k[u * 5 + v]); \
            }                                                                \
        }                                                                    \
        if (STOREF)                                                          \
            *(float4*)(OPTR) = make_float4(acc[PH][0], acc[PH][1],           \
                                           acc[PH][2], acc[PH][3]);          \
    }

    // pbase -> row i0-2, col j0-4
    const float* pbase = xim + (ptrdiff_t)(i0 - 2) * IMG_W + (j0 - 4);

    // Prologue: buffer 0 <- row i0-2 (or -inf for the top strip).
    PREF(0, topok ? pbase : ninf)

    // Head, steps s=0..3 (consume rows i0-2..i0+1, no stores).
    // Step s: phase s%5, CUR s&1, prefetch row i0+s-1 into CUR^1.
    PREF(1, topok ? pbase + 1 * IMG_W : ninf)  MATH(0, 0, 0, oim)
    PREF(0, pbase + 2 * IMG_W)                 MATH(1, 1, 0, oim)
    PREF(1, pbase + 3 * IMG_W)                 MATH(2, 0, 0, oim)
    PREF(0, pbase + 4 * IMG_W)                 MATH(3, 1, 0, oim)

    // Steady state, steps s=4..123: all loads/stores unconditional,
    // immediate offsets, pointers bumped once per 10 steps.
    const float* pb = pbase + 5 * IMG_W;             // row i0+3 (first prefetch)
    float*       ob = oim + (size_t)i0 * IMG_W + j0; // row i0 (first store)
    for (int g = 0; g < 12; ++g) {
        PREF(1, pb + 0 * IMG_W)  MATH(4, 0, 1, ob + 0 * IMG_W)
        PREF(0, pb + 1 * IMG_W)  MATH(0, 1, 1, ob + 1 * IMG_W)
        PREF(1, pb + 2 * IMG_W)  MATH(1, 0, 1, ob + 2 * IMG_W)
        PREF(0, pb + 3 * IMG_W)  MATH(2, 1, 1, ob + 3 * IMG_W)
        PREF(1, pb + 4 * IMG_W)  MATH(3, 0, 1, ob + 4 * IMG_W)
        PREF(0, pb + 5 * IMG_W)  MATH(4, 1, 1, ob + 5 * IMG_W)
        PREF(1, pb + 6 * IMG_W)  MATH(0, 0, 1, ob + 6 * IMG_W)
        PREF(0, pb + 7 * IMG_W)  MATH(1, 1, 1, ob + 7 * IMG_W)
        PREF(1, pb + 8 * IMG_W)  MATH(2, 0, 1, ob + 8 * IMG_W)
        PREF(0, pb + 9 * IMG_W)  MATH(3, 1, 1, ob + 9 * IMG_W)
        pb += 10 * IMG_W;
        ob += 10 * IMG_W;
    }
    // After loop: pb -> row i0+123 (next prefetch), ob -> output row i0+120.

    // Remainder, steps s=124..128 (unconditional; prefetch rows
    // i0+123..i0+127, all inside the image for both strips).
    PREF(1, pb + 0 * IMG_W)  MATH(4, 0, 1, ob + 0 * IMG_W)
    PREF(0, pb + 1 * IMG_W)  MATH(0, 1, 1, ob + 1 * IMG_W)
    PREF(1, pb + 2 * IMG_W)  MATH(1, 0, 1, ob + 2 * IMG_W)
    PREF(0, pb + 3 * IMG_W)  MATH(2, 1, 1, ob + 3 * IMG_W)
    PREF(1, pb + 4 * IMG_W)  MATH(3, 0, 1, ob + 4 * IMG_W)

    // Tail, steps s=129..131: prefetch rows i0+128, i0+129 (valid unless
    // bottom strip), then the final math-only step.
    PREF(0, botok ? pb + 5 * IMG_W : ninf)     MATH(4, 1, 1, ob + 5 * IMG_W)
    PREF(1, botok ? pb + 6 * IMG_W : ninf)     MATH(0, 0, 1, ob + 6 * IMG_W)
    /* no prefetch for the final step */       MATH(1, 1, 1, ob + 7 * IMG_W)

#undef PREF
#undef MATH
}

extern "C" void kernel_launch(void* const* d_in, const int* in_sizes, int n_in,
                              void* d_out, int out_size) {
    const float* x  = (const float*)d_in[0];  // (16,64,256,256)
    const float* kw = (const float*)d_in[1];  // (5,5)
    float* out = (float*)d_out;
    fill_ninf_kernel<<<1, 16>>>();
    // 4096 warp-tasks = 1024 images x 2 row-strips x 2 column-halves,
    // 1024 blocks x 4 warps: all co-resident -> one balanced wave.
    dil5x5_kernel<<<1024, 128>>>(x, kw, out);
}